// round 4
// baseline (speedup 1.0000x reference)
#include <cuda_runtime.h>
#include <cstdint>

// ---------------- problem constants ----------------
#define N_ROWS   65536      // 64 * 32 * 32 flattened vectors
#define KCODES   1024       // codebook entries
#define DDIM     256        // embedding dim (= channels)
#define B_STRIDE 262144     // 256*1024 elements per batch image (NCHW)

// ---------------- output layout (floats, concatenated in reference order) --
#define OFF_LOSS 0ll
#define OFF_QOUT 1ll
#define QOUT_LEN 16777216ll
#define OFF_PERP 16777217ll
#define OFF_ENC  16777218ll
#define ENC_LEN  67108864ll
#define OFF_QF   83886082ll

// ---------------- device scratch (no allocations allowed) ------------------
__device__ float              g_nf[N_ROWS];       // ||f||^2 per row
__device__ float              g_ne[KCODES];       // ||e||^2 per codeword
__device__ unsigned long long g_best[N_ROWS];     // packed (orderedF32(dist)<<32)|idx
__device__ int                g_idx[N_ROWS];
__device__ int                g_counts[KCODES];
__device__ double             g_loss_acc;

// monotone map fp32 -> uint32 preserving order (handles negatives)
__device__ __forceinline__ unsigned int ordf(float v) {
    unsigned int u = __float_as_uint(v);
    return (u & 0x80000000u) ? ~u : (u | 0x80000000u);
}

// ---------------- init scratch ----------------
__global__ void k_init() {
    int g = blockIdx.x * blockDim.x + threadIdx.x;
    if (g < N_ROWS) g_best[g] = 0xFFFFFFFFFFFFFFFFull;
    if (g < KCODES) g_counts[g] = 0;
    if (g == 0)     g_loss_acc = 0.0;
}

// ---------------- ||e_k||^2, one warp per codeword ----------------
__global__ void k_ne(const float* __restrict__ emb) {
    int w    = blockIdx.x * 8 + (threadIdx.x >> 5);   // 128 blocks * 8 warps = 1024
    int lane = threadIdx.x & 31;
    const float* e = emb + (size_t)w * DDIM;
    float s = 0.f;
#pragma unroll
    for (int j = 0; j < 8; j++) {
        float v = e[lane + 32 * j];
        s = __fadd_rn(s, __fmul_rn(v, v));
    }
#pragma unroll
    for (int off = 16; off; off >>= 1)
        s = __fadd_rn(s, __shfl_down_sync(0xffffffffu, s, off));
    if (lane == 0) g_ne[w] = s;
}

// ---------------- ||f_n||^2, one thread per row (SIMD16-style reduction) ---
__global__ void __launch_bounds__(256) k_nf(const float* __restrict__ inp) {
    int r  = blockIdx.x * 256 + threadIdx.x;
    int b  = r >> 10;
    int hw = r & 1023;
    const float* p = inp + (size_t)b * B_STRIDE + hw;
    float acc[16];
#pragma unroll
    for (int j = 0; j < 16; j++) acc[j] = 0.f;
    for (int s = 0; s < 16; s++) {
#pragma unroll
        for (int j = 0; j < 16; j++) {
            float v = p[(size_t)(s * 16 + j) * 1024];
            acc[j] = __fadd_rn(acc[j], __fmul_rn(v, v));
        }
    }
#pragma unroll
    for (int s2 = 8; s2; s2 >>= 1)
#pragma unroll
        for (int j = 0; j < 8; j++)
            if (j < s2) acc[j] = __fadd_rn(acc[j], acc[j + s2]);
    g_nf[r] = acc[0];
}

// ---------------- zero the encodings block (268 MB) ----------------
__global__ void k_zero_enc(float* __restrict__ out) {
    float2* p = reinterpret_cast<float2*>(out + OFF_ENC);  // OFF_ENC*4 is 8B-aligned
    const long long total  = ENC_LEN / 2;
    long long i      = (long long)blockIdx.x * blockDim.x + threadIdx.x;
    long long stride = (long long)gridDim.x * blockDim.x;
    float2 z = make_float2(0.f, 0.f);
    for (; i < total; i += stride) p[i] = z;
}

// ---------------- fused distance-GEMM + argmin ----------------
// Tile: 128 rows x 128 codes, K=256 in slices of 16. 256 threads, 8x8 micro.
__global__ void __launch_bounds__(256) k_gemm(const float* __restrict__ inp,
                                              const float* __restrict__ emb) {
    __shared__ float As[16][128];
    __shared__ float Bs[16][132];   // padded to dodge bank conflicts

    const int tid = threadIdx.x;
    const int tx  = tid & 15;       // column group
    const int ty  = tid >> 4;       // row group
    const int rowBase = blockIdx.y << 7;
    const int cBase   = blockIdx.x << 7;
    const int b   = rowBase >> 10;
    const int hw0 = rowBase & 1023;          // multiple of 128 -> 128 rows contiguous
    const float* aBase = inp + (size_t)b * B_STRIDE + hw0;

    float acc[8][8];
#pragma unroll
    for (int i = 0; i < 8; i++)
#pragma unroll
        for (int j = 0; j < 8; j++) acc[i][j] = 0.f;

    for (int kt = 0; kt < 16; kt++) {
        // load A slice [16 d][128 rows], rows are contiguous in gmem
#pragma unroll
        for (int i = 0; i < 2; i++) {
            int f  = tid + (i << 8);
            int k  = f >> 5;
            int mv = f & 31;
            float4 v = *reinterpret_cast<const float4*>(
                aBase + (size_t)(kt * 16 + k) * 1024 + (mv << 2));
            *reinterpret_cast<float4*>(&As[k][mv << 2]) = v;
        }
        // load B slice [16 d][128 codes] (transposed store)
#pragma unroll
        for (int i = 0; i < 2; i++) {
            int f  = tid + (i << 8);
            int c  = f >> 2;
            int dv = f & 3;
            float4 v = *reinterpret_cast<const float4*>(
                emb + (size_t)(cBase + c) * 256 + kt * 16 + (dv << 2));
            Bs[(dv << 2) + 0][c] = v.x;
            Bs[(dv << 2) + 1][c] = v.y;
            Bs[(dv << 2) + 2][c] = v.z;
            Bs[(dv << 2) + 3][c] = v.w;
        }
        __syncthreads();
#pragma unroll
        for (int kk = 0; kk < 16; kk++) {
            float a[8], bb[8];
            *reinterpret_cast<float4*>(&a[0])  = *reinterpret_cast<const float4*>(&As[kk][ty * 8]);
            *reinterpret_cast<float4*>(&a[4])  = *reinterpret_cast<const float4*>(&As[kk][ty * 8 + 4]);
            *reinterpret_cast<float4*>(&bb[0]) = *reinterpret_cast<const float4*>(&Bs[kk][tx * 8]);
            *reinterpret_cast<float4*>(&bb[4]) = *reinterpret_cast<const float4*>(&Bs[kk][tx * 8 + 4]);
#pragma unroll
            for (int i = 0; i < 8; i++)
#pragma unroll
                for (int j = 0; j < 8; j++)
                    acc[i][j] = fmaf(a[i], bb[j], acc[i][j]);
        }
        __syncthreads();
    }

    // epilogue: dist = fl(fl(nf+ne) - 2*C)  (2*C exact), argmin w/ first-index ties
    float nev[8];
#pragma unroll
    for (int j = 0; j < 8; j++) nev[j] = g_ne[cBase + tx * 8 + j];

#pragma unroll
    for (int i = 0; i < 8; i++) {
        int   row = rowBase + ty * 8 + i;
        float nfv = g_nf[row];
        float bv  = 3.4e38f;
        int   bc  = cBase + tx * 8;
#pragma unroll
        for (int j = 0; j < 8; j++) {
            float s = __fsub_rn(__fadd_rn(nfv, nev[j]), __fmul_rn(2.0f, acc[i][j]));
            if (s < bv) { bv = s; bc = cBase + tx * 8 + j; }   // ascending j -> first-idx ties
        }
        // reduce across the 16 tx lanes (segments of 16 within warp)
#pragma unroll
        for (int off = 8; off; off >>= 1) {
            float ov = __shfl_down_sync(0xffffffffu, bv, off, 16);
            int   oc = __shfl_down_sync(0xffffffffu, bc, off, 16);
            if (ov < bv || (ov == bv && oc < bc)) { bv = ov; bc = oc; }
        }
        if (tx == 0) {
            unsigned long long key = ((unsigned long long)ordf(bv) << 32) | (unsigned int)bc;
            atomicMin(&g_best[row], key);   // global min, tie -> smallest index
        }
    }
}

// ---------------- extract indices + histogram ----------------
__global__ void k_hist() {
    __shared__ int sc[KCODES];
    int tid = threadIdx.x;
    sc[tid] = 0;
    __syncthreads();
    int r   = blockIdx.x * 1024 + tid;
    int idx = (int)(g_best[r] & 0xFFFFFFFFull);
    g_idx[r] = idx;
    atomicAdd(&sc[idx], 1);
    __syncthreads();
    if (sc[tid]) atomicAdd(&g_counts[tid], sc[tid]);
}

// ---------------- gather + all bulk outputs + loss reduction ----------------
// 32 rows per block; codewords staged in smem for coalescing in both layouts.
__global__ void __launch_bounds__(256) k_out(const float* __restrict__ inp,
                                             const float* __restrict__ emb,
                                             float* __restrict__ out) {
    __shared__ int    sidx[32];
    __shared__ float  qs[32][257];   // +1 pad: conflict-free column reads
    __shared__ double sred[8];

    int tid   = threadIdx.x;
    int rBase = blockIdx.x << 5;

    if (tid < 32) sidx[tid] = g_idx[rBase + tid];
    __syncthreads();

    // stage codewords + write quantized_flat (coalesced along D)
    for (int r = 0; r < 32; r++) {
        float v = emb[(size_t)sidx[r] * 256 + tid];
        qs[r][tid] = v;
        out[OFF_QF + (long long)(rBase + r) * 256 + tid] = v;
    }
    if (tid < 32)
        out[OFF_ENC + (long long)(rBase + tid) * 1024 + sidx[tid]] = 1.0f;
    __syncthreads();

    // quantized_out (NCHW, same layout as inputs) + loss accumulation
    int b   = rBase >> 10;
    int hw0 = rBase & 1023;
    int r   = tid & 31;          // row within block
    int dg  = tid >> 5;          // d-phase (8 warps)
    const float* ibase = inp + (size_t)b * B_STRIDE + hw0 + r;
    float*       obase = out + OFF_QOUT + (long long)b * B_STRIDE + hw0 + r;

    double lacc = 0.0;
    for (int db = 0; db < 32; db++) {
        int   d    = (db << 3) + dg;
        float x    = ibase[(size_t)d * 1024];
        float q    = qs[r][d];
        float diff = __fsub_rn(q, x);
        obase[(long long)d * 1024] = __fadd_rn(x, diff);   // straight-through, fp32 two-step
        lacc += (double)__fmul_rn(diff, diff);
    }
#pragma unroll
    for (int off = 16; off; off >>= 1)
        lacc += __shfl_down_sync(0xffffffffu, lacc, off);
    if ((tid & 31) == 0) sred[tid >> 5] = lacc;
    __syncthreads();
    if (tid == 0) {
        double s = 0.0;
#pragma unroll
        for (int i = 0; i < 8; i++) s += sred[i];
        atomicAdd(&g_loss_acc, s);
    }
}

// ---------------- loss + perplexity ----------------
__global__ void k_final(float* __restrict__ out) {
    __shared__ double sred[32];
    int tid = threadIdx.x;   // 1024 threads, one per codeword

    int   c  = g_counts[tid];
    float pf = __fmul_rn((float)c, 1.0f / 65536.0f);       // exact
    float lf = logf(__fadd_rn(pf, 1e-10f));
    double term = (double)__fmul_rn(pf, lf);               // 0 * log(eps) = 0 when unused
#pragma unroll
    for (int off = 16; off; off >>= 1)
        term += __shfl_down_sync(0xffffffffu, term, off);
    if ((tid & 31) == 0) sred[tid >> 5] = term;
    __syncthreads();
    if (tid == 0) {
        double s = 0.0;
#pragma unroll
        for (int i = 0; i < 32; i++) s += sred[i];
        out[OFF_PERP] = expf((float)(-s));

        double mse = g_loss_acc * (1.0 / 16777216.0);
        float  m   = (float)mse;                            // q_latent == e_latent numerically
        out[OFF_LOSS] = __fadd_rn(m, __fmul_rn(0.25f, m));
    }
}

// ---------------- launch ----------------
extern "C" void kernel_launch(void* const* d_in, const int* in_sizes, int n_in,
                              void* d_out, int out_size) {
    const float* inp = (const float*)d_in[0];
    const float* emb = (const float*)d_in[1];
    if (n_in >= 2 && in_sizes[0] == KCODES * DDIM) {  // safety: order swap
        const float* t = inp; inp = emb; emb = t;
    }
    float* out = (float*)d_out;

    k_init    <<<256, 256>>>();
    k_ne      <<<128, 256>>>(emb);
    k_nf      <<<256, 256>>>(inp);
    k_zero_enc<<<2048, 256>>>(out);
    k_gemm    <<<dim3(8, 512), 256>>>(inp, emb);
    k_hist    <<<64, 1024>>>();
    k_out     <<<2048, 256>>>(inp, emb, out);
    k_final   <<<1, 1024>>>(out);
}

// round 5
// speedup vs baseline: 1.0027x; 1.0027x over previous
#include <cuda_runtime.h>
#include <cstdint>

// ---------------- problem constants ----------------
#define N_ROWS   65536      // 64 * 32 * 32 flattened vectors
#define KCODES   1024       // codebook entries
#define DDIM     256        // embedding dim (= channels)
#define B_STRIDE 262144     // 256*1024 elements per batch image (NCHW)

// ---------------- output layout (floats, concatenated in reference order) --
#define OFF_LOSS 0ll
#define OFF_QOUT 1ll
#define QOUT_LEN 16777216ll
#define OFF_PERP 16777217ll
#define OFF_ENC  16777218ll
#define ENC_LEN  67108864ll
#define OFF_QF   83886082ll

// ---------------- device scratch (no allocations allowed) ------------------
__device__ float              g_nf[N_ROWS];       // ||f||^2 per row
__device__ float              g_ne[KCODES];       // ||e||^2 per codeword
__device__ unsigned long long g_best[N_ROWS];     // packed (orderedF32(dist)<<32)|idx
__device__ int                g_idx[N_ROWS];
__device__ int                g_counts[KCODES];
__device__ double             g_loss_acc;

// monotone map fp32 -> uint32 preserving order (handles negatives)
__device__ __forceinline__ unsigned int ordf(float v) {
    unsigned int u = __float_as_uint(v);
    return (u & 0x80000000u) ? ~u : (u | 0x80000000u);
}

// ---------------- init scratch ----------------
__global__ void k_init() {
    int g = blockIdx.x * blockDim.x + threadIdx.x;
    if (g < N_ROWS) g_best[g] = 0xFFFFFFFFFFFFFFFFull;
    if (g < KCODES) g_counts[g] = 0;
    if (g == 0)     g_loss_acc = 0.0;
}

// ---------------- ||e_k||^2, one warp per codeword ----------------
__global__ void k_ne(const float* __restrict__ emb) {
    int w    = blockIdx.x * 8 + (threadIdx.x >> 5);   // 128 blocks * 8 warps = 1024
    int lane = threadIdx.x & 31;
    const float* e = emb + (size_t)w * DDIM;
    float s = 0.f;
#pragma unroll
    for (int j = 0; j < 8; j++) {
        float v = e[lane + 32 * j];
        s = __fadd_rn(s, __fmul_rn(v, v));
    }
#pragma unroll
    for (int off = 16; off; off >>= 1)
        s = __fadd_rn(s, __shfl_down_sync(0xffffffffu, s, off));
    if (lane == 0) g_ne[w] = s;
}

// ---------------- ||f_n||^2, one thread per row (SIMD16-style reduction) ---
__global__ void __launch_bounds__(256) k_nf(const float* __restrict__ inp) {
    int r  = blockIdx.x * 256 + threadIdx.x;
    int b  = r >> 10;
    int hw = r & 1023;
    const float* p = inp + (size_t)b * B_STRIDE + hw;
    float acc[16];
#pragma unroll
    for (int j = 0; j < 16; j++) acc[j] = 0.f;
    for (int s = 0; s < 16; s++) {
#pragma unroll
        for (int j = 0; j < 16; j++) {
            float v = p[(size_t)(s * 16 + j) * 1024];
            acc[j] = __fadd_rn(acc[j], __fmul_rn(v, v));
        }
    }
#pragma unroll
    for (int s2 = 8; s2; s2 >>= 1)
#pragma unroll
        for (int j = 0; j < 8; j++)
            if (j < s2) acc[j] = __fadd_rn(acc[j], acc[j + s2]);
    g_nf[r] = acc[0];
}

// ---------------- zero the encodings block (268 MB) ----------------
__global__ void k_zero_enc(float* __restrict__ out) {
    float2* p = reinterpret_cast<float2*>(out + OFF_ENC);  // OFF_ENC*4 is 8B-aligned
    const long long total  = ENC_LEN / 2;
    long long i      = (long long)blockIdx.x * blockDim.x + threadIdx.x;
    long long stride = (long long)gridDim.x * blockDim.x;
    float2 z = make_float2(0.f, 0.f);
    for (; i < total; i += stride) p[i] = z;
}

// ---------------- fused distance-GEMM + argmin ----------------
// Tile: 128 rows x 128 codes, K=256 in slices of 16. 256 threads, 8x8 micro.
__global__ void __launch_bounds__(256) k_gemm(const float* __restrict__ inp,
                                              const float* __restrict__ emb) {
    __shared__ float As[16][128];
    __shared__ float Bs[16][132];   // padded to dodge bank conflicts

    const int tid = threadIdx.x;
    const int tx  = tid & 15;       // column group
    const int ty  = tid >> 4;       // row group
    const int rowBase = blockIdx.y << 7;
    const int cBase   = blockIdx.x << 7;
    const int b   = rowBase >> 10;
    const int hw0 = rowBase & 1023;          // multiple of 128 -> 128 rows contiguous
    const float* aBase = inp + (size_t)b * B_STRIDE + hw0;

    float acc[8][8];
#pragma unroll
    for (int i = 0; i < 8; i++)
#pragma unroll
        for (int j = 0; j < 8; j++) acc[i][j] = 0.f;

    for (int kt = 0; kt < 16; kt++) {
        // load A slice [16 d][128 rows], rows are contiguous in gmem
#pragma unroll
        for (int i = 0; i < 2; i++) {
            int f  = tid + (i << 8);
            int k  = f >> 5;
            int mv = f & 31;
            float4 v = *reinterpret_cast<const float4*>(
                aBase + (size_t)(kt * 16 + k) * 1024 + (mv << 2));
            *reinterpret_cast<float4*>(&As[k][mv << 2]) = v;
        }
        // load B slice [16 d][128 codes] (transposed store)
#pragma unroll
        for (int i = 0; i < 2; i++) {
            int f  = tid + (i << 8);
            int c  = f >> 2;
            int dv = f & 3;
            float4 v = *reinterpret_cast<const float4*>(
                emb + (size_t)(cBase + c) * 256 + kt * 16 + (dv << 2));
            Bs[(dv << 2) + 0][c] = v.x;
            Bs[(dv << 2) + 1][c] = v.y;
            Bs[(dv << 2) + 2][c] = v.z;
            Bs[(dv << 2) + 3][c] = v.w;
        }
        __syncthreads();
#pragma unroll
        for (int kk = 0; kk < 16; kk++) {
            float a[8], bb[8];
            *reinterpret_cast<float4*>(&a[0])  = *reinterpret_cast<const float4*>(&As[kk][ty * 8]);
            *reinterpret_cast<float4*>(&a[4])  = *reinterpret_cast<const float4*>(&As[kk][ty * 8 + 4]);
            *reinterpret_cast<float4*>(&bb[0]) = *reinterpret_cast<const float4*>(&Bs[kk][tx * 8]);
            *reinterpret_cast<float4*>(&bb[4]) = *reinterpret_cast<const float4*>(&Bs[kk][tx * 8 + 4]);
#pragma unroll
            for (int i = 0; i < 8; i++)
#pragma unroll
                for (int j = 0; j < 8; j++)
                    acc[i][j] = fmaf(a[i], bb[j], acc[i][j]);
        }
        __syncthreads();
    }

    // epilogue: dist = fl(fl(nf+ne) - 2*C)  (2*C exact), argmin w/ first-index ties
    float nev[8];
#pragma unroll
    for (int j = 0; j < 8; j++) nev[j] = g_ne[cBase + tx * 8 + j];

#pragma unroll
    for (int i = 0; i < 8; i++) {
        int   row = rowBase + ty * 8 + i;
        float nfv = g_nf[row];
        float bv  = 3.4e38f;
        int   bc  = cBase + tx * 8;
#pragma unroll
        for (int j = 0; j < 8; j++) {
            float s = __fsub_rn(__fadd_rn(nfv, nev[j]), __fmul_rn(2.0f, acc[i][j]));
            if (s < bv) { bv = s; bc = cBase + tx * 8 + j; }   // ascending j -> first-idx ties
        }
        // reduce across the 16 tx lanes (segments of 16 within warp)
#pragma unroll
        for (int off = 8; off; off >>= 1) {
            float ov = __shfl_down_sync(0xffffffffu, bv, off, 16);
            int   oc = __shfl_down_sync(0xffffffffu, bc, off, 16);
            if (ov < bv || (ov == bv && oc < bc)) { bv = ov; bc = oc; }
        }
        if (tx == 0) {
            unsigned long long key = ((unsigned long long)ordf(bv) << 32) | (unsigned int)bc;
            atomicMin(&g_best[row], key);   // global min, tie -> smallest index
        }
    }
}

// ---------------- extract indices + histogram ----------------
__global__ void k_hist() {
    __shared__ int sc[KCODES];
    int tid = threadIdx.x;
    sc[tid] = 0;
    __syncthreads();
    int r   = blockIdx.x * 1024 + tid;
    int idx = (int)(g_best[r] & 0xFFFFFFFFull);
    g_idx[r] = idx;
    atomicAdd(&sc[idx], 1);
    __syncthreads();
    if (sc[tid]) atomicAdd(&g_counts[tid], sc[tid]);
}

// ---------------- gather + all bulk outputs + loss reduction ----------------
// 32 rows per block; codewords staged in smem for coalescing in both layouts.
__global__ void __launch_bounds__(256) k_out(const float* __restrict__ inp,
                                             const float* __restrict__ emb,
                                             float* __restrict__ out) {
    __shared__ int    sidx[32];
    __shared__ float  qs[32][257];   // +1 pad: conflict-free column reads
    __shared__ double sred[8];

    int tid   = threadIdx.x;
    int rBase = blockIdx.x << 5;

    if (tid < 32) sidx[tid] = g_idx[rBase + tid];
    __syncthreads();

    // stage codewords + write quantized_flat (coalesced along D)
    for (int r = 0; r < 32; r++) {
        float v = emb[(size_t)sidx[r] * 256 + tid];
        qs[r][tid] = v;
        out[OFF_QF + (long long)(rBase + r) * 256 + tid] = v;
    }
    if (tid < 32)
        out[OFF_ENC + (long long)(rBase + tid) * 1024 + sidx[tid]] = 1.0f;
    __syncthreads();

    // quantized_out (NCHW, same layout as inputs) + loss accumulation
    int b   = rBase >> 10;
    int hw0 = rBase & 1023;
    int r   = tid & 31;          // row within block
    int dg  = tid >> 5;          // d-phase (8 warps)
    const float* ibase = inp + (size_t)b * B_STRIDE + hw0 + r;
    float*       obase = out + OFF_QOUT + (long long)b * B_STRIDE + hw0 + r;

    double lacc = 0.0;
    for (int db = 0; db < 32; db++) {
        int   d    = (db << 3) + dg;
        float x    = ibase[(size_t)d * 1024];
        float q    = qs[r][d];
        float diff = __fsub_rn(q, x);
        obase[(long long)d * 1024] = __fadd_rn(x, diff);   // straight-through, fp32 two-step
        lacc += (double)__fmul_rn(diff, diff);
    }
#pragma unroll
    for (int off = 16; off; off >>= 1)
        lacc += __shfl_down_sync(0xffffffffu, lacc, off);
    if ((tid & 31) == 0) sred[tid >> 5] = lacc;
    __syncthreads();
    if (tid == 0) {
        double s = 0.0;
#pragma unroll
        for (int i = 0; i < 8; i++) s += sred[i];
        atomicAdd(&g_loss_acc, s);
    }
}

// ---------------- loss + perplexity ----------------
__global__ void k_final(float* __restrict__ out) {
    __shared__ double sred[32];
    int tid = threadIdx.x;   // 1024 threads, one per codeword

    int   c  = g_counts[tid];
    float pf = __fmul_rn((float)c, 1.0f / 65536.0f);       // exact
    float lf = logf(__fadd_rn(pf, 1e-10f));
    double term = (double)__fmul_rn(pf, lf);               // 0 * log(eps) = 0 when unused
#pragma unroll
    for (int off = 16; off; off >>= 1)
        term += __shfl_down_sync(0xffffffffu, term, off);
    if ((tid & 31) == 0) sred[tid >> 5] = term;
    __syncthreads();
    if (tid == 0) {
        double s = 0.0;
#pragma unroll
        for (int i = 0; i < 32; i++) s += sred[i];
        out[OFF_PERP] = expf((float)(-s));

        double mse = g_loss_acc * (1.0 / 16777216.0);
        float  m   = (float)mse;                            // q_latent == e_latent numerically
        out[OFF_LOSS] = __fadd_rn(m, __fmul_rn(0.25f, m));
    }
}

// ---------------- launch ----------------
extern "C" void kernel_launch(void* const* d_in, const int* in_sizes, int n_in,
                              void* d_out, int out_size) {
    const float* inp = (const float*)d_in[0];
    const float* emb = (const float*)d_in[1];
    if (n_in >= 2 && in_sizes[0] == KCODES * DDIM) {  // safety: order swap
        const float* t = inp; inp = emb; emb = t;
    }
    float* out = (float*)d_out;

    k_init    <<<256, 256>>>();
    k_ne      <<<128, 256>>>(emb);
    k_nf      <<<256, 256>>>(inp);
    k_zero_enc<<<2048, 256>>>(out);
    k_gemm    <<<dim3(8, 512), 256>>>(inp, emb);
    k_hist    <<<64, 1024>>>();
    k_out     <<<2048, 256>>>(inp, emb, out);
    k_final   <<<1, 1024>>>(out);
}